// round 6
// baseline (speedup 1.0000x reference)
#include <cuda_runtime.h>
#include <cuda_bf16.h>
#include <math_constants.h>

// Problem shape (fixed by the dataset)
#define BB 8
#define HH 3
#define PP 4096
#define NS 64                   // q-splits per batch (fine-grained blocks)
#define TPQ (PP / NS)           // 64 q points per split
#define NPAIR (TPQ / 2)         // 32 packed q-pairs per split
#define TP 128                  // threads per chamfer block
#define PPT 4                   // p-points per thread
#define PBLK (TP * PPT)         // 512 p per block
#define NBLK 128                // combine partial sums
#define NPTS (BB * PP)

// global min (as uint bits of nonneg float) per [h][b*PP+p]; reset to 0x7F7F7F7F
__device__ unsigned int g_minbits[HH * NPTS];
__device__ float g_partial[NBLK];

// ---- f32x2 helpers (Blackwell packed fp32: add/sub/mul/fma only) ----------
__device__ __forceinline__ unsigned long long pack2(float lo, float hi) {
    unsigned long long d;
    asm("mov.b64 %0, {%1, %2};" : "=l"(d) : "f"(lo), "f"(hi));
    return d;
}
__device__ __forceinline__ unsigned long long fma2(unsigned long long a,
                                                   unsigned long long b,
                                                   unsigned long long c) {
    unsigned long long d;
    asm("fma.rn.f32x2 %0, %1, %2, %3;" : "=l"(d) : "l"(a), "l"(b), "l"(c));
    return d;
}
// scalar min of packed result into two scalar accumulators
__device__ __forceinline__ void min2(float& a, float& b, unsigned long long t) {
    float lo, hi;
    asm("mov.b64 {%0, %1}, %2;" : "=f"(lo), "=f"(hi) : "l"(t));
    a = fminf(a, lo);
    b = fminf(b, hi);
}

// normalized plane normals + offset for batch b (fp32, Newton-refined rsqrt)
__device__ __forceinline__ void load_normals(const float* __restrict__ planes,
                                             int b, float nx[HH], float ny[HH],
                                             float nz[HH], float nc[HH]) {
#pragma unroll
    for (int h = 0; h < HH; h++) {
        const float* pl = planes + (b * HH + h) * 4;
        float x = pl[0], y = pl[1], z = pl[2];
        float nn  = x * x + y * y + z * z;
        float inv = rsqrtf(nn);
        inv = inv * (1.5f - 0.5f * nn * inv * inv);
        nx[h] = x * inv; ny[h] = y * inv; nz[h] = z * inv; nc[h] = pl[3];
    }
}

// ---------------------------------------------------------------------------
// Main kernel: block = (p-tile of 512, q-split of 64, batch). 4096 blocks.
// Inner loop per q-pair: 4 LDS + 24 FFMA2 + 24 FMNMX covering 4p x 2q x 3h.
// Epilogue: val = max(min + |x_p|^2, 0) >= 0, bitwise atomicMin (exact,
// order-independent -> deterministic).
// ---------------------------------------------------------------------------
__global__ __launch_bounds__(TP, 6)
void chamfer_kernel(const float* __restrict__ planes,
                    const float* __restrict__ pts) {
    __shared__ ulonglong2         sA[NPAIR];
    __shared__ ulonglong2         sB[NPAIR];
    __shared__ ulonglong2         sC[NPAIR];
    __shared__ unsigned long long sD[NPAIR];

    const int t    = threadIdx.x;
    const int tile = blockIdx.x;        // 0 .. PP/PBLK-1
    const int spl  = blockIdx.y;        // 0 .. NS-1
    const int b    = blockIdx.z;        // 0 .. BB-1

    float nx[HH], ny[HH], nz[HH], nc[HH];
    load_normals(planes, b, nx, ny, nz, nc);

    // ---- stage q-tile (NPAIR=32, threads 0..31 stage) ----
    const int qstart = b * PP + spl * TPQ;
    if (t < NPAIR) {
        const int j = t;
        const float* q = pts + (qstart + 2 * j) * 3;
        float x0 = q[0], y0 = q[1], z0 = q[2];
        float x1 = q[3], y1 = q[4], z1 = q[5];
        float w0 = x0 * x0 + y0 * y0 + z0 * z0;
        float w1 = x1 * x1 + y1 * y1 + z1 * z1;
        float d0[HH], d1[HH];
#pragma unroll
        for (int h = 0; h < HH; h++) {
            d0[h] = nx[h] * x0 + ny[h] * y0 + nz[h] * z0 + nc[h];
            d1[h] = nx[h] * x1 + ny[h] * y1 + nz[h] * z1 + nc[h];
        }
        ulonglong2 A, B, C;
        A.x = pack2(x0, x1);       A.y = pack2(y0, y1);
        B.x = pack2(z0, z1);       B.y = pack2(w0, w1);
        C.x = pack2(d0[0], d1[0]); C.y = pack2(d0[1], d1[1]);
        sA[j] = A; sB[j] = B; sC[j] = C;
        sD[j] = pack2(d0[2], d1[2]);
    }

    // ---- per-thread p constants: PPT p-points, stride TP apart ----
    unsigned long long MX[PPT], MY[PPT], MZ[PPT];
    unsigned long long Q0[PPT], Q1[PPT], Q2[PPT];
    float x2p[PPT];
    float m0a[PPT], m0b[PPT], m1a[PPT], m1b[PPT], m2a[PPT], m2b[PPT];
#pragma unroll
    for (int k = 0; k < PPT; k++) {
        const int p = tile * PBLK + k * TP + t;
        const float* P = pts + (b * PP + p) * 3;
        float ax = P[0], ay = P[1], az = P[2];
        float e0 = nx[0] * ax + ny[0] * ay + nz[0] * az + nc[0];
        float e1 = nx[1] * ax + ny[1] * ay + nz[1] * az + nc[1];
        float e2 = nx[2] * ax + ny[2] * ay + nz[2] * az + nc[2];
        MX[k] = pack2(-2.f * ax, -2.f * ax);
        MY[k] = pack2(-2.f * ay, -2.f * ay);
        MZ[k] = pack2(-2.f * az, -2.f * az);
        Q0[k] = pack2(4.f * e0, 4.f * e0);
        Q1[k] = pack2(4.f * e1, 4.f * e1);
        Q2[k] = pack2(4.f * e2, 4.f * e2);
        x2p[k] = ax * ax + ay * ay + az * az;
        m0a[k] = m0b[k] = CUDART_INF_F;
        m1a[k] = m1b[k] = CUDART_INF_F;
        m2a[k] = m2b[k] = CUDART_INF_F;
    }

    __syncthreads();

#pragma unroll 4
    for (int j = 0; j < NPAIR; j++) {
        ulonglong2 A = sA[j];
        ulonglong2 B = sB[j];
        ulonglong2 C = sC[j];
        unsigned long long D2 = sD[j];

#pragma unroll
        for (int k = 0; k < PPT; k++) {
            // acc = w_q - 2 x_p . x_q   (|x_p|^2 added in epilogue)
            unsigned long long acc = fma2(MX[k], A.x, B.y);
            acc = fma2(MY[k], A.y, acc);
            acc = fma2(MZ[k], B.x, acc);
            min2(m0a[k], m0b[k], fma2(Q0[k], C.x, acc));
            min2(m1a[k], m1b[k], fma2(Q1[k], C.y, acc));
            min2(m2a[k], m2b[k], fma2(Q2[k], D2,  acc));
        }
    }

    // epilogue: clamp to >=0 and bitwise atomicMin (uint order == float order
    // for nonneg floats; exact & commutative -> deterministic)
#pragma unroll
    for (int k = 0; k < PPT; k++) {
        const int i = b * PP + tile * PBLK + k * TP + t;
        float v0 = fmaxf(fminf(m0a[k], m0b[k]) + x2p[k], 0.0f);
        float v1 = fmaxf(fminf(m1a[k], m1b[k]) + x2p[k], 0.0f);
        float v2 = fmaxf(fminf(m2a[k], m2b[k]) + x2p[k], 0.0f);
        atomicMin(&g_minbits[0 * NPTS + i], __float_as_uint(v0));
        atomicMin(&g_minbits[1 * NPTS + i], __float_as_uint(v1));
        atomicMin(&g_minbits[2 * NPTS + i], __float_as_uint(v2));
    }
}

// ---------------------------------------------------------------------------
// Combine: sum the 3 head-mins per point, deterministic block tree-reduce.
// ---------------------------------------------------------------------------
__global__ __launch_bounds__(256)
void combine_kernel() {
    __shared__ float red[256];
    const int i = blockIdx.x * 256 + threadIdx.x;   // 0 .. B*P-1

    float s = __uint_as_float(g_minbits[0 * NPTS + i])
            + __uint_as_float(g_minbits[1 * NPTS + i])
            + __uint_as_float(g_minbits[2 * NPTS + i]);

    red[threadIdx.x] = s;
    __syncthreads();
#pragma unroll
    for (int off = 128; off > 0; off >>= 1) {
        if (threadIdx.x < off) red[threadIdx.x] += red[threadIdx.x + off];
        __syncthreads();
    }
    if (threadIdx.x == 0) g_partial[blockIdx.x] = red[0];
}

// ---------------------------------------------------------------------------
// Finalize: parallel fp32 tree-reduce of partials + per-batch reg loss.
// ---------------------------------------------------------------------------
__global__ __launch_bounds__(128)
void finalize_kernel(const float* __restrict__ planes,
                     float* __restrict__ out) {
    __shared__ float red[128];
    __shared__ float regs[BB];
    const int t = threadIdx.x;

    red[t] = g_partial[t];
    __syncthreads();
#pragma unroll
    for (int off = 64; off > 0; off >>= 1) {
        if (t < off) red[t] += red[t + off];
        __syncthreads();
    }

    if (t < BB) {
        float nx[HH], ny[HH], nz[HH], nc[HH];
        load_normals(planes, t, nx, ny, nz, nc);
        float acc = 0.0f;
#pragma unroll
        for (int i = 0; i < HH; i++)
#pragma unroll
            for (int j = 0; j < HH; j++) {
                float g = nx[i] * nx[j] + ny[i] * ny[j] + nz[i] * nz[j]
                        - (i == j ? 1.0f : 0.0f);
                acc += g * g;
            }
        regs[t] = sqrtf(acc);
    }
    __syncthreads();

    if (t == 0) {
        float reg = 0.0f;
#pragma unroll
        for (int b = 0; b < BB; b++) reg += regs[b];
        // cham_x == cham_y by reflection symmetry -> factor 2
        float refl = 2.0f * red[0] / (float)(BB * PP);
        out[0] = refl + 25.0f * reg;
    }
}

// ---------------------------------------------------------------------------
extern "C" void kernel_launch(void* const* d_in, const int* in_sizes, int n_in,
                              void* d_out, int out_size) {
    const float* planes = (const float*)d_in[0];   // (8, 3, 4)
    const float* pts    = (const float*)d_in[1];   // (8, 4096, 3)
    // d_in[2], d_in[3] (voxel/cp grids) are unused by the reference.

    // reset min buffer to 0x7F7F7F7F (= 3.39e38 as float) — capturable memset
    void* minbits_addr = nullptr;
    cudaGetSymbolAddress(&minbits_addr, g_minbits);
    cudaMemsetAsync(minbits_addr, 0x7F, (size_t)HH * NPTS * sizeof(unsigned int));

    dim3 grid(PP / PBLK, NS, BB);   // (8, 64, 8) = 4096 blocks
    chamfer_kernel<<<grid, TP>>>(planes, pts);

    combine_kernel<<<NBLK, 256>>>();
    finalize_kernel<<<1, 128>>>(planes, (float*)d_out);
}

// round 7
// speedup vs baseline: 1.0048x; 1.0048x over previous
#include <cuda_runtime.h>
#include <cuda_bf16.h>
#include <math_constants.h>

// Problem shape (fixed by the dataset)
#define BB 8
#define HH 3
#define PP 4096
#define NS 64                   // q-splits per batch (fine-grained blocks)
#define TPQ (PP / NS)           // 64 q points per split
#define NPAIR (TPQ / 2)         // 32 packed q-pairs per split
#define TP 128                  // threads per chamfer block
#define PPT 4                   // p-points per thread
#define PBLK (TP * PPT)         // 512 p per block
#define NBLK 128                // combine partial sums
#define NPTS (BB * PP)

// global min (as uint bits of nonneg float) per [h][b*PP+p]; reset to 0x7F7F7F7F
__device__ unsigned int g_minbits[HH * NPTS];
__device__ float g_partial[NBLK];

// ---- f32x2 helpers (Blackwell packed fp32: add/sub/mul/fma only) ----------
__device__ __forceinline__ unsigned long long pack2(float lo, float hi) {
    unsigned long long d;
    asm("mov.b64 %0, {%1, %2};" : "=l"(d) : "f"(lo), "f"(hi));
    return d;
}
__device__ __forceinline__ unsigned long long fma2(unsigned long long a,
                                                   unsigned long long b,
                                                   unsigned long long c) {
    unsigned long long d;
    asm("fma.rn.f32x2 %0, %1, %2, %3;" : "=l"(d) : "l"(a), "l"(b), "l"(c));
    return d;
}
// scalar min of packed result into two scalar accumulators
__device__ __forceinline__ void min2(float& a, float& b, unsigned long long t) {
    float lo, hi;
    asm("mov.b64 {%0, %1}, %2;" : "=f"(lo), "=f"(hi) : "l"(t));
    a = fminf(a, lo);
    b = fminf(b, hi);
}

// normalized plane normals + offset for batch b (fp32, Newton-refined rsqrt)
__device__ __forceinline__ void load_normals(const float* __restrict__ planes,
                                             int b, float nx[HH], float ny[HH],
                                             float nz[HH], float nc[HH]) {
#pragma unroll
    for (int h = 0; h < HH; h++) {
        const float* pl = planes + (b * HH + h) * 4;
        float x = pl[0], y = pl[1], z = pl[2];
        float nn  = x * x + y * y + z * z;
        float inv = rsqrtf(nn);
        inv = inv * (1.5f - 0.5f * nn * inv * inv);
        nx[h] = x * inv; ny[h] = y * inv; nz[h] = z * inv; nc[h] = pl[3];
    }
}

// ---------------------------------------------------------------------------
// Main kernel: block = (p-tile of 512, q-split of 64, batch). 4096 blocks.
// Inner loop per q-pair: 4 LDS + 24 FFMA2 + 24 FMNMX covering 4p x 2q x 3h.
// Epilogue: val = max(min + |x_p|^2, 0) >= 0, bitwise atomicMin (exact,
// order-independent -> deterministic).
// ---------------------------------------------------------------------------
__global__ __launch_bounds__(TP, 6)
void chamfer_kernel(const float* __restrict__ planes,
                    const float* __restrict__ pts) {
    __shared__ ulonglong2         sA[NPAIR];
    __shared__ ulonglong2         sB[NPAIR];
    __shared__ ulonglong2         sC[NPAIR];
    __shared__ unsigned long long sD[NPAIR];

    const int t    = threadIdx.x;
    const int tile = blockIdx.x;        // 0 .. PP/PBLK-1
    const int spl  = blockIdx.y;        // 0 .. NS-1
    const int b    = blockIdx.z;        // 0 .. BB-1

    float nx[HH], ny[HH], nz[HH], nc[HH];
    load_normals(planes, b, nx, ny, nz, nc);

    // ---- stage q-tile (NPAIR=32, threads 0..31 stage) ----
    const int qstart = b * PP + spl * TPQ;
    if (t < NPAIR) {
        const int j = t;
        const float* q = pts + (qstart + 2 * j) * 3;
        float x0 = q[0], y0 = q[1], z0 = q[2];
        float x1 = q[3], y1 = q[4], z1 = q[5];
        float w0 = x0 * x0 + y0 * y0 + z0 * z0;
        float w1 = x1 * x1 + y1 * y1 + z1 * z1;
        float d0[HH], d1[HH];
#pragma unroll
        for (int h = 0; h < HH; h++) {
            d0[h] = nx[h] * x0 + ny[h] * y0 + nz[h] * z0 + nc[h];
            d1[h] = nx[h] * x1 + ny[h] * y1 + nz[h] * z1 + nc[h];
        }
        ulonglong2 A, B, C;
        A.x = pack2(x0, x1);       A.y = pack2(y0, y1);
        B.x = pack2(z0, z1);       B.y = pack2(w0, w1);
        C.x = pack2(d0[0], d1[0]); C.y = pack2(d0[1], d1[1]);
        sA[j] = A; sB[j] = B; sC[j] = C;
        sD[j] = pack2(d0[2], d1[2]);
    }

    // ---- per-thread p constants: PPT p-points, stride TP apart ----
    unsigned long long MX[PPT], MY[PPT], MZ[PPT];
    unsigned long long Q0[PPT], Q1[PPT], Q2[PPT];
    float x2p[PPT];
    float m0a[PPT], m0b[PPT], m1a[PPT], m1b[PPT], m2a[PPT], m2b[PPT];
#pragma unroll
    for (int k = 0; k < PPT; k++) {
        const int p = tile * PBLK + k * TP + t;
        const float* P = pts + (b * PP + p) * 3;
        float ax = P[0], ay = P[1], az = P[2];
        float e0 = nx[0] * ax + ny[0] * ay + nz[0] * az + nc[0];
        float e1 = nx[1] * ax + ny[1] * ay + nz[1] * az + nc[1];
        float e2 = nx[2] * ax + ny[2] * ay + nz[2] * az + nc[2];
        MX[k] = pack2(-2.f * ax, -2.f * ax);
        MY[k] = pack2(-2.f * ay, -2.f * ay);
        MZ[k] = pack2(-2.f * az, -2.f * az);
        Q0[k] = pack2(4.f * e0, 4.f * e0);
        Q1[k] = pack2(4.f * e1, 4.f * e1);
        Q2[k] = pack2(4.f * e2, 4.f * e2);
        x2p[k] = ax * ax + ay * ay + az * az;
        m0a[k] = m0b[k] = CUDART_INF_F;
        m1a[k] = m1b[k] = CUDART_INF_F;
        m2a[k] = m2b[k] = CUDART_INF_F;
    }

    __syncthreads();

#pragma unroll 4
    for (int j = 0; j < NPAIR; j++) {
        ulonglong2 A = sA[j];
        ulonglong2 B = sB[j];
        ulonglong2 C = sC[j];
        unsigned long long D2 = sD[j];

#pragma unroll
        for (int k = 0; k < PPT; k++) {
            // acc = w_q - 2 x_p . x_q   (|x_p|^2 added in epilogue)
            unsigned long long acc = fma2(MX[k], A.x, B.y);
            acc = fma2(MY[k], A.y, acc);
            acc = fma2(MZ[k], B.x, acc);
            min2(m0a[k], m0b[k], fma2(Q0[k], C.x, acc));
            min2(m1a[k], m1b[k], fma2(Q1[k], C.y, acc));
            min2(m2a[k], m2b[k], fma2(Q2[k], D2,  acc));
        }
    }

    // epilogue: clamp to >=0 and bitwise atomicMin (uint order == float order
    // for nonneg floats; exact & commutative -> deterministic)
#pragma unroll
    for (int k = 0; k < PPT; k++) {
        const int i = b * PP + tile * PBLK + k * TP + t;
        float v0 = fmaxf(fminf(m0a[k], m0b[k]) + x2p[k], 0.0f);
        float v1 = fmaxf(fminf(m1a[k], m1b[k]) + x2p[k], 0.0f);
        float v2 = fmaxf(fminf(m2a[k], m2b[k]) + x2p[k], 0.0f);
        atomicMin(&g_minbits[0 * NPTS + i], __float_as_uint(v0));
        atomicMin(&g_minbits[1 * NPTS + i], __float_as_uint(v1));
        atomicMin(&g_minbits[2 * NPTS + i], __float_as_uint(v2));
    }
}

// ---------------------------------------------------------------------------
// Combine: sum the 3 head-mins per point, deterministic block tree-reduce.
// ---------------------------------------------------------------------------
__global__ __launch_bounds__(256)
void combine_kernel() {
    __shared__ float red[256];
    const int i = blockIdx.x * 256 + threadIdx.x;   // 0 .. B*P-1

    float s = __uint_as_float(g_minbits[0 * NPTS + i])
            + __uint_as_float(g_minbits[1 * NPTS + i])
            + __uint_as_float(g_minbits[2 * NPTS + i]);

    red[threadIdx.x] = s;
    __syncthreads();
#pragma unroll
    for (int off = 128; off > 0; off >>= 1) {
        if (threadIdx.x < off) red[threadIdx.x] += red[threadIdx.x + off];
        __syncthreads();
    }
    if (threadIdx.x == 0) g_partial[blockIdx.x] = red[0];
}

// ---------------------------------------------------------------------------
// Finalize: parallel fp32 tree-reduce of partials + per-batch reg loss.
// ---------------------------------------------------------------------------
__global__ __launch_bounds__(128)
void finalize_kernel(const float* __restrict__ planes,
                     float* __restrict__ out) {
    __shared__ float red[128];
    __shared__ float regs[BB];
    const int t = threadIdx.x;

    red[t] = g_partial[t];
    __syncthreads();
#pragma unroll
    for (int off = 64; off > 0; off >>= 1) {
        if (t < off) red[t] += red[t + off];
        __syncthreads();
    }

    if (t < BB) {
        float nx[HH], ny[HH], nz[HH], nc[HH];
        load_normals(planes, t, nx, ny, nz, nc);
        float acc = 0.0f;
#pragma unroll
        for (int i = 0; i < HH; i++)
#pragma unroll
            for (int j = 0; j < HH; j++) {
                float g = nx[i] * nx[j] + ny[i] * ny[j] + nz[i] * nz[j]
                        - (i == j ? 1.0f : 0.0f);
                acc += g * g;
            }
        regs[t] = sqrtf(acc);
    }
    __syncthreads();

    if (t == 0) {
        float reg = 0.0f;
#pragma unroll
        for (int b = 0; b < BB; b++) reg += regs[b];
        // cham_x == cham_y by reflection symmetry -> factor 2
        float refl = 2.0f * red[0] / (float)(BB * PP);
        out[0] = refl + 25.0f * reg;
    }
}

// ---------------------------------------------------------------------------
extern "C" void kernel_launch(void* const* d_in, const int* in_sizes, int n_in,
                              void* d_out, int out_size) {
    const float* planes = (const float*)d_in[0];   // (8, 3, 4)
    const float* pts    = (const float*)d_in[1];   // (8, 4096, 3)
    // d_in[2], d_in[3] (voxel/cp grids) are unused by the reference.

    // reset min buffer to 0x7F7F7F7F (= 3.39e38 as float) — capturable memset
    void* minbits_addr = nullptr;
    cudaGetSymbolAddress(&minbits_addr, g_minbits);
    cudaMemsetAsync(minbits_addr, 0x7F, (size_t)HH * NPTS * sizeof(unsigned int));

    dim3 grid(PP / PBLK, NS, BB);   // (8, 64, 8) = 4096 blocks
    chamfer_kernel<<<grid, TP>>>(planes, pts);

    combine_kernel<<<NBLK, 256>>>();
    finalize_kernel<<<1, 128>>>(planes, (float*)d_out);
}